// round 9
// baseline (speedup 1.0000x reference)
#include <cuda_runtime.h>

#define NN   100000
#define NE   1600000
#define FIN  128
#define HID  64
#define NCLS 40

// ---- scratch (device globals; ONLY referenced inside device code) ----
__device__ __align__(16) float g_h   [NN * HID];   // GEMM output, pre-scaled by dinv[row]
__device__ __align__(16) float g_out [NN * HID];   // aggregated output (width 64)
__device__ float g_dinv[NN];
__device__ int   g_cnt [NN];          // in-degree (excl self-loop)
__device__ int   g_cur [NN];          // fill cursors
__device__ int   g_off [NN + 1];      // CSR offsets
__device__ int   g_csr [NE];          // src only, grouped by dst
__device__ int   g_is64;              // edge-index dtype probe

// ------------------------------------------------------------------
// dtype probe: int64 edge values < 2^31 => all odd 32-bit words zero.
// ------------------------------------------------------------------
__global__ void k_detect(const unsigned int* __restrict__ w) {
    __shared__ int nz;
    if (threadIdx.x == 0) nz = 0;
    __syncthreads();
    int found = 0;
    for (int i = 1 + threadIdx.x * 128; i < 2 * NE; i += 256 * 128)
        if (w[i] != 0u) found = 1;
    if (found) atomicOr(&nz, 1);
    __syncthreads();
    if (threadIdx.x == 0) g_is64 = (nz == 0) ? 1 : 0;
}

__device__ __forceinline__ int edge_at(const void* eiv, int idx) {
    long long v = g_is64 ? ((const long long*)eiv)[idx] : (long long)((const int*)eiv)[idx];
    return (v < 0) ? 0 : (v >= NN ? NN - 1 : (int)v);
}

// ------------------------------------------------------------------
// CSR build: zero -> histogram -> dinv -> scan -> fill (src only)
// ------------------------------------------------------------------
__global__ void k_zero() {
    int i = blockIdx.x * blockDim.x + threadIdx.x;
    if (i < NN) { g_cnt[i] = 0; g_cur[i] = 0; }
}

__global__ void k_hist(const void* __restrict__ eiv) {
    int e = blockIdx.x * blockDim.x + threadIdx.x;
    if (e >= NE) return;
    atomicAdd(&g_cnt[edge_at(eiv, NE + e)], 1);
}

__global__ void k_dinv() {
    int i = blockIdx.x * blockDim.x + threadIdx.x;
    if (i < NN) g_dinv[i] = rsqrtf((float)(g_cnt[i] + 1));   // +1 self-loop
}

#define SCAN_T 1024
__global__ void k_scan() {
    int t = threadIdx.x;
    const int chunk = (NN + SCAN_T - 1) / SCAN_T;
    int start = t * chunk;
    int end = start + chunk; if (end > NN) end = NN;
    int s = 0;
    for (int i = start; i < end; i++) { int c = g_cnt[i]; g_off[i] = s; s += c; }
    __shared__ int sums[SCAN_T];
    sums[t] = s;
    __syncthreads();
    for (int o = 1; o < SCAN_T; o <<= 1) {
        int v = (t >= o) ? sums[t - o] : 0;
        __syncthreads();
        sums[t] += v;
        __syncthreads();
    }
    int base = (t == 0) ? 0 : sums[t - 1];
    for (int i = start; i < end; i++) g_off[i] += base;
    if (t == SCAN_T - 1) g_off[NN] = sums[SCAN_T - 1];
}

__global__ void k_fill(const void* __restrict__ eiv) {
    int e = blockIdx.x * blockDim.x + threadIdx.x;
    if (e >= NE) return;
    int s = edge_at(eiv, e);
    int d = edge_at(eiv, NE + e);
    int idx = g_off[d] + atomicAdd(&g_cur[d], 1);
    g_csr[idx] = s;
}

// ------------------------------------------------------------------
// GEMM: g_h[n,F] = dinv[n] * act(Xsrc[n,K]) @ W[K,F]
// ------------------------------------------------------------------
template <int K, int F, int RF, int RM, bool HASB, bool FROMG>
__global__ void k_gemm(const float* __restrict__ X,
                       const float* __restrict__ W,
                       const float* __restrict__ bin) {
    constexpr int NF = F / RF;
    constexpr int MT = 256 / NF;
    constexpr int TM = MT * RM;

    const float4* __restrict__ X4 =
        FROMG ? (const float4*)g_out : (const float4*)X;

    __shared__ float Ws[K * F];
    __shared__ float Bs[K];

    int tid = threadIdx.x;
    for (int i = tid; i < K * F; i += 256) Ws[i] = W[i];
    if (HASB) for (int i = tid; i < K; i += 256) Bs[i] = bin[i];
    __syncthreads();

    int fth  = tid % NF;
    int mth  = tid / NF;
    int f0   = fth * RF;
    int row0 = blockIdx.x * TM + mth * RM;

    float acc[RM][RF];
#pragma unroll
    for (int m = 0; m < RM; m++)
#pragma unroll
        for (int j = 0; j < RF; j++) acc[m][j] = 0.f;

#pragma unroll
    for (int k4 = 0; k4 < K; k4 += 4) {
        float xr[RM][4];
#pragma unroll
        for (int m = 0; m < RM; m++) {
            int r = row0 + m;
            float4 v = (r < NN) ? X4[(r * K + k4) >> 2]
                                : make_float4(0.f, 0.f, 0.f, 0.f);
            if (HASB) {
                v.x = fmaxf(v.x + Bs[k4 + 0], 0.f);
                v.y = fmaxf(v.y + Bs[k4 + 1], 0.f);
                v.z = fmaxf(v.z + Bs[k4 + 2], 0.f);
                v.w = fmaxf(v.w + Bs[k4 + 3], 0.f);
            }
            xr[m][0] = v.x; xr[m][1] = v.y; xr[m][2] = v.z; xr[m][3] = v.w;
        }
#pragma unroll
        for (int kk = 0; kk < 4; kk++) {
#pragma unroll
            for (int j = 0; j < RF; j++) {
                float wv = Ws[(k4 + kk) * F + f0 + j];
#pragma unroll
                for (int m = 0; m < RM; m++)
                    acc[m][j] = fmaf(xr[m][kk], wv, acc[m][j]);
            }
        }
    }

#pragma unroll
    for (int m = 0; m < RM; m++) {
        int r = row0 + m;
        if (r < NN) {
            float di = g_dinv[r];
#pragma unroll
            for (int j = 0; j < RF; j++)
                g_h[r * F + f0 + j] = acc[m][j] * di;
        }
    }
}

// ------------------------------------------------------------------
// Aggregation F=64: warp per dst node; 16 float4 lanes per row;
// halves of the warp process even/odd edges (2 edges/iter, 8 in batch).
// out[dst] = dinv[dst] * (h'[dst] + sum h'[src])
// ------------------------------------------------------------------
__global__ void k_agg64() {
    int gw   = (blockIdx.x * blockDim.x + threadIdx.x) >> 5;
    int lane = threadIdx.x & 31;
    if (gw >= NN) return;

    const float4* __restrict__ h4 = (const float4*)g_h;   // row = 16 float4
    int half = lane >> 4;
    int sub  = lane & 15;

    float4 a = (half == 0) ? h4[gw * 16 + sub] : make_float4(0.f, 0.f, 0.f, 0.f);

    int b = g_off[gw], e = g_off[gw + 1];
    int i = b;
    for (; i + 8 <= e; i += 8) {
        int s0 = g_csr[i     + half];
        int s1 = g_csr[i + 2 + half];
        int s2 = g_csr[i + 4 + half];
        int s3 = g_csr[i + 6 + half];
        float4 h0 = h4[s0 * 16 + sub];
        float4 h1 = h4[s1 * 16 + sub];
        float4 hv = h4[s2 * 16 + sub];
        float4 h3 = h4[s3 * 16 + sub];
        a.x += h0.x + h1.x + hv.x + h3.x;
        a.y += h0.y + h1.y + hv.y + h3.y;
        a.z += h0.z + h1.z + hv.z + h3.z;
        a.w += h0.w + h1.w + hv.w + h3.w;
    }
    for (; i < e; i += 2) {
        int idx = i + half;
        if (idx < e) {
            float4 hv = h4[g_csr[idx] * 16 + sub];
            a.x += hv.x; a.y += hv.y; a.z += hv.z; a.w += hv.w;
        }
    }

    // combine halves (shfls read pre-add values)
    float tx = __shfl_xor_sync(0xFFFFFFFFu, a.x, 16);
    float ty = __shfl_xor_sync(0xFFFFFFFFu, a.y, 16);
    float tz = __shfl_xor_sync(0xFFFFFFFFu, a.z, 16);
    float tw = __shfl_xor_sync(0xFFFFFFFFu, a.w, 16);
    a.x += tx; a.y += ty; a.z += tz; a.w += tw;

    if (half == 0) {
        float di = g_dinv[gw];
        a.x *= di; a.y *= di; a.z *= di; a.w *= di;
        ((float4*)g_out)[gw * 16 + sub] = a;
    }
}

// ------------------------------------------------------------------
// Layer-3 aggregation (F=40: 10 float4 lanes per row, 3 edge groups)
// fused with bias+relu+log_softmax. Writes final output.
// ------------------------------------------------------------------
__global__ void k_agg40_lsm(const float* __restrict__ b3, float* __restrict__ out) {
    int gw   = (blockIdx.x * blockDim.x + threadIdx.x) >> 5;
    int lane = threadIdx.x & 31;
    if (gw >= NN) return;

    const float4* __restrict__ h4 = (const float4*)g_h;   // row = 10 float4
    int grp = (lane < 10) ? 0 : (lane < 20 ? 1 : (lane < 30 ? 2 : 3));
    int sub = lane - grp * 10;
    bool act = grp < 3;

    float4 a = (grp == 0) ? h4[gw * 10 + sub] : make_float4(0.f, 0.f, 0.f, 0.f);

    int b = g_off[gw], e = g_off[gw + 1];
    int i = b;
    for (; i + 12 <= e; i += 12) {
        if (act) {
            int s0 = g_csr[i     + grp];
            int s1 = g_csr[i + 3 + grp];
            int s2 = g_csr[i + 6 + grp];
            int s3 = g_csr[i + 9 + grp];
            float4 h0 = h4[s0 * 10 + sub];
            float4 h1 = h4[s1 * 10 + sub];
            float4 hv = h4[s2 * 10 + sub];
            float4 h3 = h4[s3 * 10 + sub];
            a.x += h0.x + h1.x + hv.x + h3.x;
            a.y += h0.y + h1.y + hv.y + h3.y;
            a.z += h0.z + h1.z + hv.z + h3.z;
            a.w += h0.w + h1.w + hv.w + h3.w;
        }
    }
    for (; i < e; i += 3) {
        int idx = i + grp;
        if (act && idx < e) {
            float4 hv = h4[g_csr[idx] * 10 + sub];
            a.x += hv.x; a.y += hv.y; a.z += hv.z; a.w += hv.w;
        }
    }

    // combine 3 groups: read pre-modification values, then add
    float t1x = __shfl_down_sync(0xFFFFFFFFu, a.x, 10);
    float t1y = __shfl_down_sync(0xFFFFFFFFu, a.y, 10);
    float t1z = __shfl_down_sync(0xFFFFFFFFu, a.z, 10);
    float t1w = __shfl_down_sync(0xFFFFFFFFu, a.w, 10);
    float t2x = __shfl_down_sync(0xFFFFFFFFu, a.x, 20);
    float t2y = __shfl_down_sync(0xFFFFFFFFu, a.y, 20);
    float t2z = __shfl_down_sync(0xFFFFFFFFu, a.z, 20);
    float t2w = __shfl_down_sync(0xFFFFFFFFu, a.w, 20);
    a.x += t1x + t2x; a.y += t1y + t2y; a.z += t1z + t2z; a.w += t1w + t2w;

    bool res = (lane < 10);   // lanes holding 4 final classes each

    // dinv scale + bias + relu
    float4 v = make_float4(-1e30f, -1e30f, -1e30f, -1e30f);
    if (res) {
        float di = g_dinv[gw];
        float4 bb = ((const float4*)b3)[sub];
        v.x = fmaxf(a.x * di + bb.x, 0.f);
        v.y = fmaxf(a.y * di + bb.y, 0.f);
        v.z = fmaxf(a.z * di + bb.z, 0.f);
        v.w = fmaxf(a.w * di + bb.w, 0.f);
    }

    // log_softmax over 40 values (10 lanes x 4)
    float m = fmaxf(fmaxf(v.x, v.y), fmaxf(v.z, v.w));
#pragma unroll
    for (int o = 16; o > 0; o >>= 1)
        m = fmaxf(m, __shfl_xor_sync(0xFFFFFFFFu, m, o));

    float s = res ? (__expf(v.x - m) + __expf(v.y - m) +
                     __expf(v.z - m) + __expf(v.w - m)) : 0.f;
#pragma unroll
    for (int o = 16; o > 0; o >>= 1)
        s += __shfl_xor_sync(0xFFFFFFFFu, s, o);

    float lse = m + __logf(s);
    if (res) {
        float4 r = make_float4(v.x - lse, v.y - lse, v.z - lse, v.w - lse);
        ((float4*)out)[gw * 10 + sub] = r;
    }
}

extern "C" void kernel_launch(void* const* d_in, const int* in_sizes, int n_in,
                              void* d_out, int out_size) {
    // ---- bind inputs BY ELEMENT COUNT (robust to metadata ordering) ----
    const float* x  = 0;
    const void*  ei = 0;
    const float *W1 = 0, *W2 = 0, *W3 = 0, *b1 = 0, *b2 = 0, *b3 = 0;
    for (int i = 0; i < n_in; i++) {
        long long sz = in_sizes[i];
        const void* p = d_in[i];
        if      (sz == (long long)NN * FIN)  x  = (const float*)p;
        else if (sz == 2LL * NE)             ei = p;
        else if (sz == FIN * HID)            W1 = (const float*)p;
        else if (sz == HID * HID)            W2 = (const float*)p;
        else if (sz == HID * NCLS)           W3 = (const float*)p;
        else if (sz == NCLS)                 b3 = (const float*)p;
        else if (sz == HID) {
            if (!b1) b1 = (const float*)p; else b2 = (const float*)p;
        }
    }
    float* out = (float*)d_out;
    if (!x || !ei || !W1 || !W2 || !W3 || !b1 || !b2 || !b3) return;

    const int TB = 256;
    int gN = (NN + TB - 1) / TB;
    int gE = (NE + TB - 1) / TB;
    int gW = (NN * 32 + TB - 1) / TB;   // warp-per-node grids

    // --- CSR build ---
    k_detect<<<1, TB>>>((const unsigned int*)ei);
    k_zero<<<gN, TB>>>();
    k_hist<<<gE, TB>>>(ei);
    k_dinv<<<gN, TB>>>();
    k_scan<<<1, SCAN_T>>>();
    k_fill<<<gE, TB>>>(ei);

    // --- layer 1: 128 -> 64 ---
    {
        constexpr int TM = (256 / (64 / 4)) * 4;   // 64 rows/block
        k_gemm<FIN, HID, 4, 4, false, false><<<(NN + TM - 1) / TM, TB>>>(x, W1, b3);
        k_agg64<<<gW, TB>>>();
    }
    // --- layer 2: 64 -> 64 (relu(prev + b1) fused into GEMM input) ---
    {
        constexpr int TM = (256 / (64 / 4)) * 4;
        k_gemm<HID, HID, 4, 4, true, true><<<(NN + TM - 1) / TM, TB>>>(x, W2, b1);
        k_agg64<<<gW, TB>>>();
    }
    // --- layer 3: 64 -> 40 + fused bias/relu/log_softmax ---
    {
        constexpr int TM = (256 / (40 / 5)) * 4;   // 128 rows/block
        k_gemm<HID, NCLS, 5, 4, true, true><<<(NN + TM - 1) / TM, TB>>>(x, W3, b2);
        k_agg40_lsm<<<gW, TB>>>(b3, out);
    }
}

// round 13
// speedup vs baseline: 1.5657x; 1.5657x over previous
#include <cuda_runtime.h>

#define NN   100000
#define NE   1600000
#define FIN  128
#define HID  64
#define NCLS 40

// ---- scratch (device globals; ONLY referenced inside device code) ----
__device__ __align__(16) float g_h   [NN * HID];   // GEMM output, pre-scaled by dinv[row]
__device__ __align__(16) float g_out [NN * HID];   // aggregated output (width 64)
__device__ float g_dinv[NN];
__device__ int   g_cnt [NN];          // in-degree (excl self-loop)
__device__ int   g_cur [NN];          // fill cursors
__device__ int   g_off [NN + 1];      // CSR offsets
__device__ int   g_csr [NE];          // src only, grouped by dst
__device__ int   g_is64;              // edge-index dtype probe

// ------------------------------------------------------------------
// dtype probe: int64 edge values < 2^31 => all odd 32-bit words zero.
// ------------------------------------------------------------------
__global__ void k_detect(const unsigned int* __restrict__ w) {
    __shared__ int nz;
    if (threadIdx.x == 0) nz = 0;
    __syncthreads();
    int found = 0;
    for (int i = 1 + threadIdx.x * 128; i < 2 * NE; i += 256 * 128)
        if (w[i] != 0u) found = 1;
    if (found) atomicOr(&nz, 1);
    __syncthreads();
    if (threadIdx.x == 0) g_is64 = (nz == 0) ? 1 : 0;
}

__device__ __forceinline__ int edge_at(const void* eiv, int idx) {
    long long v = g_is64 ? ((const long long*)eiv)[idx] : (long long)((const int*)eiv)[idx];
    return (v < 0) ? 0 : (v >= NN ? NN - 1 : (int)v);
}

// ------------------------------------------------------------------
// CSR build: zero -> histogram -> dinv -> scan -> fill (src only)
// ------------------------------------------------------------------
__global__ void k_zero() {
    int i = blockIdx.x * blockDim.x + threadIdx.x;
    if (i < NN) { g_cnt[i] = 0; g_cur[i] = 0; }
}

__global__ void k_hist(const void* __restrict__ eiv) {
    int e = blockIdx.x * blockDim.x + threadIdx.x;
    if (e >= NE) return;
    atomicAdd(&g_cnt[edge_at(eiv, NE + e)], 1);
}

__global__ void k_dinv() {
    int i = blockIdx.x * blockDim.x + threadIdx.x;
    if (i < NN) g_dinv[i] = rsqrtf((float)(g_cnt[i] + 1));   // +1 self-loop
}

#define SCAN_T 1024
__global__ void k_scan() {
    int t = threadIdx.x;
    const int chunk = (NN + SCAN_T - 1) / SCAN_T;
    int start = t * chunk;
    int end = start + chunk; if (end > NN) end = NN;
    int s = 0;
    for (int i = start; i < end; i++) { int c = g_cnt[i]; g_off[i] = s; s += c; }
    __shared__ int sums[SCAN_T];
    sums[t] = s;
    __syncthreads();
    for (int o = 1; o < SCAN_T; o <<= 1) {
        int v = (t >= o) ? sums[t - o] : 0;
        __syncthreads();
        sums[t] += v;
        __syncthreads();
    }
    int base = (t == 0) ? 0 : sums[t - 1];
    for (int i = start; i < end; i++) g_off[i] += base;
    if (t == SCAN_T - 1) g_off[NN] = sums[SCAN_T - 1];
}

__global__ void k_fill(const void* __restrict__ eiv) {
    int e = blockIdx.x * blockDim.x + threadIdx.x;
    if (e >= NE) return;
    int s = edge_at(eiv, e);
    int d = edge_at(eiv, NE + e);
    int idx = g_off[d] + atomicAdd(&g_cur[d], 1);
    g_csr[idx] = s;
}

// ------------------------------------------------------------------
// GEMM: g_h[n,F] = dinv[n] * act(Xsrc[n,K]) @ W[K,F]
// ------------------------------------------------------------------
template <int K, int F, int RF, int RM, bool HASB, bool FROMG>
__global__ void k_gemm(const float* __restrict__ X,
                       const float* __restrict__ W,
                       const float* __restrict__ bin) {
    constexpr int NF = F / RF;
    constexpr int MT = 256 / NF;
    constexpr int TM = MT * RM;

    const float4* __restrict__ X4 =
        FROMG ? (const float4*)g_out : (const float4*)X;

    __shared__ float Ws[K * F];
    __shared__ float Bs[K];

    int tid = threadIdx.x;
    for (int i = tid; i < K * F; i += 256) Ws[i] = W[i];
    if (HASB) for (int i = tid; i < K; i += 256) Bs[i] = bin[i];
    __syncthreads();

    int fth  = tid % NF;
    int mth  = tid / NF;
    int f0   = fth * RF;
    int row0 = blockIdx.x * TM + mth * RM;

    float acc[RM][RF];
#pragma unroll
    for (int m = 0; m < RM; m++)
#pragma unroll
        for (int j = 0; j < RF; j++) acc[m][j] = 0.f;

#pragma unroll
    for (int k4 = 0; k4 < K; k4 += 4) {
        float xr[RM][4];
#pragma unroll
        for (int m = 0; m < RM; m++) {
            int r = row0 + m;
            float4 v = (r < NN) ? X4[(r * K + k4) >> 2]
                                : make_float4(0.f, 0.f, 0.f, 0.f);
            if (HASB) {
                v.x = fmaxf(v.x + Bs[k4 + 0], 0.f);
                v.y = fmaxf(v.y + Bs[k4 + 1], 0.f);
                v.z = fmaxf(v.z + Bs[k4 + 2], 0.f);
                v.w = fmaxf(v.w + Bs[k4 + 3], 0.f);
            }
            xr[m][0] = v.x; xr[m][1] = v.y; xr[m][2] = v.z; xr[m][3] = v.w;
        }
#pragma unroll
        for (int kk = 0; kk < 4; kk++) {
#pragma unroll
            for (int j = 0; j < RF; j++) {
                float wv = Ws[(k4 + kk) * F + f0 + j];
#pragma unroll
                for (int m = 0; m < RM; m++)
                    acc[m][j] = fmaf(xr[m][kk], wv, acc[m][j]);
            }
        }
    }

#pragma unroll
    for (int m = 0; m < RM; m++) {
        int r = row0 + m;
        if (r < NN) {
            float di = g_dinv[r];
#pragma unroll
            for (int j = 0; j < RF; j++)
                g_h[r * F + f0 + j] = acc[m][j] * di;
        }
    }
}

// ------------------------------------------------------------------
// Aggregation F=64: warp per dst node, ALL 32 lanes on one row
// (float2 each), 8-edge batches for MLP. CSR = bare src index.
// out[dst] = dinv[dst] * (h'[dst] + sum h'[src])
// ------------------------------------------------------------------
__global__ void k_agg64() {
    int gw   = (blockIdx.x * blockDim.x + threadIdx.x) >> 5;
    int lane = threadIdx.x & 31;
    if (gw >= NN) return;

    const float2* __restrict__ h2 = (const float2*)g_h;   // row = 32 float2

    float2 a = h2[gw * 32 + lane];    // self term (h' already has dinv[src])

    int b = g_off[gw], e = g_off[gw + 1];
    int i = b;
    for (; i + 8 <= e; i += 8) {
        int s0 = g_csr[i    ], s1 = g_csr[i + 1];
        int s2 = g_csr[i + 2], s3 = g_csr[i + 3];
        int s4 = g_csr[i + 4], s5 = g_csr[i + 5];
        int s6 = g_csr[i + 6], s7 = g_csr[i + 7];
        float2 h0 = h2[s0 * 32 + lane];
        float2 h1 = h2[s1 * 32 + lane];
        float2 hv2 = h2[s2 * 32 + lane];
        float2 h3 = h2[s3 * 32 + lane];
        float2 h4v = h2[s4 * 32 + lane];
        float2 h5 = h2[s5 * 32 + lane];
        float2 h6 = h2[s6 * 32 + lane];
        float2 h7 = h2[s7 * 32 + lane];
        a.x += (h0.x + h1.x) + (hv2.x + h3.x) + (h4v.x + h5.x) + (h6.x + h7.x);
        a.y += (h0.y + h1.y) + (hv2.y + h3.y) + (h4v.y + h5.y) + (h6.y + h7.y);
    }
    for (; i < e; i++) {
        float2 hv = h2[g_csr[i] * 32 + lane];
        a.x += hv.x; a.y += hv.y;
    }

    float di = g_dinv[gw];
    a.x *= di; a.y *= di;
    ((float2*)g_out)[gw * 32 + lane] = a;
}

// ------------------------------------------------------------------
// Layer-3 aggregation (F=40, 20 float2 lanes) fused with
// bias+relu+log_softmax. Writes final output directly.
// ------------------------------------------------------------------
__global__ void k_agg40_lsm(const float* __restrict__ b3, float* __restrict__ out) {
    int gw   = (blockIdx.x * blockDim.x + threadIdx.x) >> 5;
    int lane = threadIdx.x & 31;
    if (gw >= NN) return;

    const float2* __restrict__ h2 = (const float2*)g_h;   // row = 20 float2
    bool act = lane < 20;
    int  sl  = act ? lane : 0;                 // safe lane index

    float2 a = act ? h2[gw * 20 + sl] : make_float2(0.f, 0.f);

    int b = g_off[gw], e = g_off[gw + 1];
    int i = b;
    for (; i + 8 <= e; i += 8) {
        int s0 = g_csr[i    ], s1 = g_csr[i + 1];
        int s2 = g_csr[i + 2], s3 = g_csr[i + 3];
        int s4 = g_csr[i + 4], s5 = g_csr[i + 5];
        int s6 = g_csr[i + 6], s7 = g_csr[i + 7];
        if (act) {
            float2 h0 = h2[s0 * 20 + sl];
            float2 h1 = h2[s1 * 20 + sl];
            float2 hv2 = h2[s2 * 20 + sl];
            float2 h3 = h2[s3 * 20 + sl];
            float2 h4v = h2[s4 * 20 + sl];
            float2 h5 = h2[s5 * 20 + sl];
            float2 h6 = h2[s6 * 20 + sl];
            float2 h7 = h2[s7 * 20 + sl];
            a.x += (h0.x + h1.x) + (hv2.x + h3.x) + (h4v.x + h5.x) + (h6.x + h7.x);
            a.y += (h0.y + h1.y) + (hv2.y + h3.y) + (h4v.y + h5.y) + (h6.y + h7.y);
        }
    }
    for (; i < e; i++) {
        if (act) {
            float2 hv = h2[g_csr[i] * 20 + sl];
            a.x += hv.x; a.y += hv.y;
        }
    }

    // dinv scale + bias + relu (two classes per active lane)
    float v0 = -1e30f, v1 = -1e30f;
    if (act) {
        float di = g_dinv[gw];
        float2 bb = ((const float2*)b3)[sl];
        v0 = fmaxf(a.x * di + bb.x, 0.f);
        v1 = fmaxf(a.y * di + bb.y, 0.f);
    }

    // log_softmax over 40 values spread across 20 lanes x 2
    float m = fmaxf(v0, v1);
#pragma unroll
    for (int o = 16; o > 0; o >>= 1)
        m = fmaxf(m, __shfl_xor_sync(0xFFFFFFFFu, m, o));

    float s = act ? (__expf(v0 - m) + __expf(v1 - m)) : 0.f;
#pragma unroll
    for (int o = 16; o > 0; o >>= 1)
        s += __shfl_xor_sync(0xFFFFFFFFu, s, o);

    float lse = m + __logf(s);
    if (act) {
        float2 r = make_float2(v0 - lse, v1 - lse);
        ((float2*)out)[gw * 20 + sl] = r;
    }
}

extern "C" void kernel_launch(void* const* d_in, const int* in_sizes, int n_in,
                              void* d_out, int out_size) {
    // ---- bind inputs BY ELEMENT COUNT (robust to metadata ordering) ----
    const float* x  = 0;
    const void*  ei = 0;
    const float *W1 = 0, *W2 = 0, *W3 = 0, *b1 = 0, *b2 = 0, *b3 = 0;
    for (int i = 0; i < n_in; i++) {
        long long sz = in_sizes[i];
        const void* p = d_in[i];
        if      (sz == (long long)NN * FIN)  x  = (const float*)p;
        else if (sz == 2LL * NE)             ei = p;
        else if (sz == FIN * HID)            W1 = (const float*)p;
        else if (sz == HID * HID)            W2 = (const float*)p;
        else if (sz == HID * NCLS)           W3 = (const float*)p;
        else if (sz == NCLS)                 b3 = (const float*)p;
        else if (sz == HID) {
            if (!b1) b1 = (const float*)p; else b2 = (const float*)p;
        }
    }
    float* out = (float*)d_out;
    if (!x || !ei || !W1 || !W2 || !W3 || !b1 || !b2 || !b3) return;

    const int TB = 256;
    int gN = (NN + TB - 1) / TB;
    int gE = (NE + TB - 1) / TB;
    int gW = (NN * 32 + TB - 1) / TB;   // warp-per-node grids

    // --- CSR build ---
    k_detect<<<1, TB>>>((const unsigned int*)ei);
    k_zero<<<gN, TB>>>();
    k_hist<<<gE, TB>>>(ei);
    k_dinv<<<gN, TB>>>();
    k_scan<<<1, SCAN_T>>>();
    k_fill<<<gE, TB>>>(ei);

    // --- layer 1: 128 -> 64 ---
    {
        constexpr int TM = (256 / (64 / 4)) * 4;   // 64 rows/block
        k_gemm<FIN, HID, 4, 4, false, false><<<(NN + TM - 1) / TM, TB>>>(x, W1, b3);
        k_agg64<<<gW, TB>>>();
    }
    // --- layer 2: 64 -> 64 (relu(prev + b1) fused into GEMM input) ---
    {
        constexpr int TM = (256 / (64 / 4)) * 4;
        k_gemm<HID, HID, 4, 4, true, true><<<(NN + TM - 1) / TM, TB>>>(x, W2, b1);
        k_agg64<<<gW, TB>>>();
    }
    // --- layer 3: 64 -> 40 + fused bias/relu/log_softmax ---
    {
        constexpr int TM = (256 / (40 / 5)) * 4;   // 128 rows/block
        k_gemm<HID, NCLS, 5, 4, true, true><<<(NN + TM - 1) / TM, TB>>>(x, W3, b2);
        k_agg40_lsm<<<gW, TB>>>(b3, out);
    }
}